// round 1
// baseline (speedup 1.0000x reference)
#include <cuda_runtime.h>
#include <math.h>

// Problem constants
// B=2, T=2048, D=3584, N=16, K=8, H=256, WINDOW=1024, SOFT_CAP=50, SCALAR=0.0625

// ---------------- scratch (static device globals; allocation-free) ----------
__device__ float g_W[3584 * 8192];     // packed [D][N*H + 2*K*H] weight (117 MB)
__device__ float g_QKV[4096 * 8192];   // [B*T][ q(4096) | k(2048) | v(2048) ]  (134 MB)
__device__ float g_ENC[4096 * 4096];   // attention output, [B*T][N*H] (67 MB)

// ---------------- weight pack: W[d][j] ---------------------------------------
// j in [0,4096): q_w[n][d][h], n=j>>8, h=j&255
// j in [4096,8192): kv_w[ck][d][h], ck=(j-4096)>>8  (ck<8 -> K, ck>=8 -> V)
__global__ __launch_bounds__(256) void pack_w_kernel(const float* __restrict__ qw,
                                                     const float* __restrict__ kvw)
{
    int idx = blockIdx.x * 256 + threadIdx.x;   // < 3584*8192
    int j = idx & 8191;
    int d = idx >> 13;
    float v;
    if (j < 4096) {
        int n = j >> 8, h = j & 255;
        v = qw[((size_t)n * 3584 + d) * 256 + h];
    } else {
        int jj = j - 4096;
        int ck = jj >> 8, h = jj & 255;
        v = kvw[((size_t)ck * 3584 + d) * 256 + h];
    }
    g_W[idx] = v;
}

// ---------------- generic 128x128x8 register-tiled SGEMM ---------------------
// C[M,N] = A[M,K] * B[K,N], all row-major. M,N multiples of 128; K multiple of 8.
__global__ __launch_bounds__(256) void sgemm128x128(const float* __restrict__ A,
                                                    const float* __restrict__ B,
                                                    float* __restrict__ C,
                                                    int M, int N, int K)
{
    __shared__ float As[8][132];   // transposed A tile, padded
    __shared__ float Bs[8][128];

    const int tid  = threadIdx.x;
    const int tx   = tid & 15;
    const int ty   = tid >> 4;
    const int arow = tid >> 1;
    const int acol = (tid & 1) << 2;
    const int brow = tid >> 5;
    const int bcol = (tid & 31) << 2;

    const float* Ap = A + (size_t)(blockIdx.y * 128 + arow) * K + acol;
    const float* Bp = B + (size_t)brow * N + blockIdx.x * 128 + bcol;

    float acc[8][8];
#pragma unroll
    for (int i = 0; i < 8; i++)
#pragma unroll
        for (int j = 0; j < 8; j++) acc[i][j] = 0.0f;

    for (int k0 = 0; k0 < K; k0 += 8) {
        float4 av = *(const float4*)(Ap + k0);
        float4 bv = *(const float4*)(Bp + (size_t)k0 * N);
        __syncthreads();
        As[acol + 0][arow] = av.x;
        As[acol + 1][arow] = av.y;
        As[acol + 2][arow] = av.z;
        As[acol + 3][arow] = av.w;
        *(float4*)&Bs[brow][bcol] = bv;
        __syncthreads();
#pragma unroll
        for (int kk = 0; kk < 8; kk++) {
            float af[8], bf[8];
            *(float4*)(af + 0) = *(const float4*)&As[kk][ty * 8 + 0];
            *(float4*)(af + 4) = *(const float4*)&As[kk][ty * 8 + 4];
            *(float4*)(bf + 0) = *(const float4*)&Bs[kk][tx * 8 + 0];
            *(float4*)(bf + 4) = *(const float4*)&Bs[kk][tx * 8 + 4];
#pragma unroll
            for (int i = 0; i < 8; i++)
#pragma unroll
                for (int j = 0; j < 8; j++)
                    acc[i][j] = fmaf(af[i], bf[j], acc[i][j]);
        }
    }

    float* Cp = C + (size_t)(blockIdx.y * 128 + ty * 8) * N + blockIdx.x * 128 + tx * 8;
#pragma unroll
    for (int i = 0; i < 8; i++) {
        *(float4*)(Cp + (size_t)i * N + 0) = make_float4(acc[i][0], acc[i][1], acc[i][2], acc[i][3]);
        *(float4*)(Cp + (size_t)i * N + 4) = make_float4(acc[i][4], acc[i][5], acc[i][6], acc[i][7]);
    }
}

// ---------------- RoPE (+ q scaling), in place on g_QKV ----------------------
// grid.x = B*T (=4096), grid.y = 24 heads (0..15 q, 16..23 k), 128 threads (= H/2)
__global__ __launch_bounds__(128) void rope_kernel(const int* __restrict__ segpos)
{
    int bt = blockIdx.x;
    int hh = blockIdx.y;
    int i  = threadIdx.x;                 // 0..127
    float* p = g_QKV + (size_t)bt * 8192 + hh * 256;
    float pos = (float)segpos[bt];
    float ts  = powf(10000.0f, (float)i * (1.0f / 128.0f));
    float ang = pos / ts;
    float s, c;
    sincosf(ang, &s, &c);
    float a  = p[i];
    float b2 = p[i + 128];
    float o1 = a * c - b2 * s;
    float o2 = b2 * c + a * s;
    if (hh < 16) { o1 *= 0.0625f; o2 *= 0.0625f; }   // SCALAR on q heads
    p[i]       = o1;
    p[i + 128] = o2;
}

// ---------------- windowed flash attention ----------------------------------
// grid: (T/64, N, B). block: 256 threads. 64-query tile, 32-key chunks.
// smem: Qs[256][64] (h-major), Ks[256][32] (h-major), Vs[32][256], Ps[32][68]
#define ATTN_SMEM ((256*64 + 256*32 + 32*256 + 32*68) * 4)

__global__ __launch_bounds__(256) void attn_kernel()
{
    extern __shared__ float sm[];
    float* Qs = sm;                 // 16384 floats
    float* Ks = Qs + 256 * 64;      // 8192
    float* Vs = Ks + 256 * 32;      // 8192
    float* Ps = Vs + 32 * 256;      // 32*68 (padded rows)

    const int t0  = blockIdx.x << 6;
    const int n   = blockIdx.y;
    const int b   = blockIdx.z;
    const int kh  = n >> 1;                  // G = N/K = 2
    const int tid = threadIdx.x;

    const float* base = g_QKV + (size_t)b * 2048 * 8192;

    // load Q tile transposed: Qs[h][t]
    {
        int t  = tid & 63;
        int h0 = (tid >> 6) << 2;
        const float* qp = base + (size_t)(t0 + t) * 8192 + n * 256;
#pragma unroll
        for (int h = h0; h < 256; h += 16) {
            float4 v = *(const float4*)(qp + h);
            Qs[(h + 0) * 64 + t] = v.x;
            Qs[(h + 1) * 64 + t] = v.y;
            Qs[(h + 2) * 64 + t] = v.z;
            Qs[(h + 3) * 64 + t] = v.w;
        }
    }

    const int qt = tid >> 4;   // q-group: rows qt*4 .. qt*4+3
    const int st = tid & 15;   // score: key cols st*2; PV: h lanes st*4 (+j*64)

    float m[4] = {-1e30f, -1e30f, -1e30f, -1e30f};
    float l[4] = {0.f, 0.f, 0.f, 0.f};
    float O[4][16];
#pragma unroll
    for (int i = 0; i < 4; i++)
#pragma unroll
        for (int j = 0; j < 16; j++) O[i][j] = 0.f;

    int smin = t0 - 1023; if (smin < 0) smin = 0;
    const int c0 = smin >> 5;
    const int c1 = (t0 + 63) >> 5;

    const int ks  = tid & 31;            // K loader: key row
    const int kh0 = (tid >> 5) << 2;     // K loader: h start
    const int vs  = tid >> 3;            // V loader: key row
    const int vh0 = (tid & 7) << 2;      // V loader: h start

    for (int c = c0; c <= c1; c++) {
        const int sg0 = c << 5;
        __syncthreads();   // previous PV done; safe to overwrite K/V (also orders Q on 1st iter)

        // K chunk transposed: Ks[h][s]
        {
            const float* kp = base + (size_t)(sg0 + ks) * 8192 + 4096 + kh * 256;
#pragma unroll
            for (int h = kh0; h < 256; h += 32) {
                float4 v = *(const float4*)(kp + h);
                Ks[(h + 0) * 32 + ks] = v.x;
                Ks[(h + 1) * 32 + ks] = v.y;
                Ks[(h + 2) * 32 + ks] = v.z;
                Ks[(h + 3) * 32 + ks] = v.w;
            }
        }
        // V chunk natural: Vs[s][h]
        {
            const float* vp = base + (size_t)(sg0 + vs) * 8192 + 6144 + kh * 256;
#pragma unroll
            for (int h = vh0; h < 256; h += 32)
                *(float4*)&Vs[vs * 256 + h] = *(const float4*)(vp + h);
        }
        __syncthreads();

        // scores: 4q x 2s per thread, reduce over h=256
        float acc[4][2] = {{0.f,0.f},{0.f,0.f},{0.f,0.f},{0.f,0.f}};
#pragma unroll 8
        for (int h = 0; h < 256; h++) {
            float4 qv = *(const float4*)&Qs[h * 64 + (qt << 2)];
            float2 kv = *(const float2*)&Ks[h * 32 + (st << 1)];
            acc[0][0] = fmaf(qv.x, kv.x, acc[0][0]);
            acc[0][1] = fmaf(qv.x, kv.y, acc[0][1]);
            acc[1][0] = fmaf(qv.y, kv.x, acc[1][0]);
            acc[1][1] = fmaf(qv.y, kv.y, acc[1][1]);
            acc[2][0] = fmaf(qv.z, kv.x, acc[2][0]);
            acc[2][1] = fmaf(qv.z, kv.y, acc[2][1]);
            acc[3][0] = fmaf(qv.w, kv.x, acc[3][0]);
            acc[3][1] = fmaf(qv.w, kv.y, acc[3][1]);
        }

        // soft cap + window mask + online softmax (per q row, 16-lane groups)
        float alpha[4];
#pragma unroll
        for (int i = 0; i < 4; i++) {
            const int tq = t0 + (qt << 2) + i;
            const int sg = sg0 + (st << 1);
            float v0 = 50.0f * tanhf(acc[i][0] * 0.02f);
            float v1 = 50.0f * tanhf(acc[i][1] * 0.02f);
            bool ok0 = (sg     <= tq) && (sg     >= tq - 1023);
            bool ok1 = (sg + 1 <= tq) && (sg + 1 >= tq - 1023);
            float r0 = ok0 ? v0 : -1e30f;
            float r1 = ok1 ? v1 : -1e30f;
            float rmax = fmaxf(r0, r1);
#pragma unroll
            for (int o = 8; o > 0; o >>= 1)
                rmax = fmaxf(rmax, __shfl_xor_sync(0xffffffffu, rmax, o));
            float mnew = fmaxf(m[i], rmax);
            alpha[i] = __expf(m[i] - mnew);
            float p0 = __expf(r0 - mnew);
            float p1 = __expf(r1 - mnew);
            // NOTE: fully-masked chunks before the window yield p=1 "junk";
            // it is annihilated by alpha=exp(-1e30-m_real)=0 at the first valid chunk.
            Ps[(st * 2 + 0) * 68 + (qt << 2) + i] = p0;
            Ps[(st * 2 + 1) * 68 + (qt << 2) + i] = p1;
            float rsum = p0 + p1;
#pragma unroll
            for (int o = 8; o > 0; o >>= 1)
                rsum += __shfl_xor_sync(0xffffffffu, rsum, o);
            l[i] = l[i] * alpha[i] + rsum;
            m[i] = mnew;
        }
        __syncthreads();   // Ps visible to all

        // rescale O, then O += P * V (4q x 16h per thread)
#pragma unroll
        for (int i = 0; i < 4; i++) {
            float a = alpha[i];
#pragma unroll
            for (int j = 0; j < 16; j++) O[i][j] *= a;
        }
        for (int s = 0; s < 32; s++) {
            float4 pv = *(const float4*)&Ps[s * 68 + (qt << 2)];
#pragma unroll
            for (int j = 0; j < 4; j++) {
                float4 vv = *(const float4*)&Vs[s * 256 + j * 64 + (st << 2)];
                O[0][j*4+0] = fmaf(pv.x, vv.x, O[0][j*4+0]);
                O[0][j*4+1] = fmaf(pv.x, vv.y, O[0][j*4+1]);
                O[0][j*4+2] = fmaf(pv.x, vv.z, O[0][j*4+2]);
                O[0][j*4+3] = fmaf(pv.x, vv.w, O[0][j*4+3]);
                O[1][j*4+0] = fmaf(pv.y, vv.x, O[1][j*4+0]);
                O[1][j*4+1] = fmaf(pv.y, vv.y, O[1][j*4+1]);
                O[1][j*4+2] = fmaf(pv.y, vv.z, O[1][j*4+2]);
                O[1][j*4+3] = fmaf(pv.y, vv.w, O[1][j*4+3]);
                O[2][j*4+0] = fmaf(pv.z, vv.x, O[2][j*4+0]);
                O[2][j*4+1] = fmaf(pv.z, vv.y, O[2][j*4+1]);
                O[2][j*4+2] = fmaf(pv.z, vv.z, O[2][j*4+2]);
                O[2][j*4+3] = fmaf(pv.z, vv.w, O[2][j*4+3]);
                O[3][j*4+0] = fmaf(pv.w, vv.x, O[3][j*4+0]);
                O[3][j*4+1] = fmaf(pv.w, vv.y, O[3][j*4+1]);
                O[3][j*4+2] = fmaf(pv.w, vv.z, O[3][j*4+2]);
                O[3][j*4+3] = fmaf(pv.w, vv.w, O[3][j*4+3]);
            }
        }
    }

    // epilogue: normalize, store to g_ENC[(b*T+t)][n*256+h]
    float* ep = g_ENC + ((size_t)(b * 2048 + t0)) * 4096 + n * 256;
#pragma unroll
    for (int i = 0; i < 4; i++) {
        float inv = 1.0f / l[i];
        int tq = (qt << 2) + i;
#pragma unroll
        for (int j = 0; j < 4; j++) {
            float4 o4 = make_float4(O[i][j*4+0] * inv, O[i][j*4+1] * inv,
                                    O[i][j*4+2] * inv, O[i][j*4+3] * inv);
            *(float4*)(ep + (size_t)tq * 4096 + j * 64 + (st << 2)) = o4;
        }
    }
}

// ---------------- launch ------------------------------------------------------
extern "C" void kernel_launch(void* const* d_in, const int* in_sizes, int n_in,
                              void* d_out, int out_size)
{
    const float* x      = (const float*)d_in[0];   // (B,T,D) f32
    const int*   segpos = (const int*)  d_in[1];   // (B,T) i32
    // d_in[2] = attn_mask (deterministic tril; mask computed analytically)
    const float* qw     = (const float*)d_in[3];   // (N,D,H)
    const float* kvw    = (const float*)d_in[4];   // (2,K,D,H)
    const float* ow     = (const float*)d_in[5];   // (N,H,D) == row-major (N*H, D)
    float* out = (float*)d_out;                    // (B,T,D)

    float *W, *QKV, *ENC;
    cudaGetSymbolAddress((void**)&W,   g_W);
    cudaGetSymbolAddress((void**)&QKV, g_QKV);
    cudaGetSymbolAddress((void**)&ENC, g_ENC);

    // 1) pack weights -> W[3584][8192]
    pack_w_kernel<<<(3584 * 8192) / 256, 256>>>(qw, kvw);

    // 2) qkv = x @ W   (4096 x 8192, K=3584)
    sgemm128x128<<<dim3(8192 / 128, 4096 / 128), 256>>>(x, W, QKV, 4096, 8192, 3584);

    // 3) RoPE + q scaling in place (q heads 0..15, k heads 16..23)
    rope_kernel<<<dim3(4096, 24), 128>>>(segpos);

    // 4) windowed flash attention -> ENC[4096][4096]
    cudaFuncSetAttribute(attn_kernel, cudaFuncAttributeMaxDynamicSharedMemorySize, ATTN_SMEM);
    attn_kernel<<<dim3(2048 / 64, 16, 2), 256, ATTN_SMEM>>>();

    // 5) out = ENC @ o_w  (4096 x 3584, K=4096)
    sgemm128x128<<<dim3(3584 / 128, 4096 / 128), 256>>>(ENC, ow, out, 4096, 3584, 4096);
}

// round 3
// speedup vs baseline: 3.0418x; 3.0418x over previous
#include <cuda_runtime.h>
#include <cuda_fp16.h>
#include <math.h>
#include <stdint.h>

// B=2, T=2048, D=3584, N=16, K=8, H=256, WINDOW=1024, SOFT_CAP=50, SCALAR=0.0625

// ---------------- scratch (allocation-free device globals) -------------------
__device__ unsigned short g_Xh  [4096u * 3584u];  // x in fp16
__device__ unsigned short g_Wth [8192u * 3584u];  // packed qkv weight, [j][d] K-major fp16
__device__ unsigned short g_OWth[3584u * 4096u];  // packed o_w^T, [d][j] K-major fp16
__device__ float          g_QKV [4096u * 8192u];  // [B*T][ q | k | v ] fp32
__device__ unsigned short g_ENCh[4096u * 4096u];  // attention output fp16

// ---------------- helpers -----------------------------------------------------
__device__ __forceinline__ uint32_t smem_u32(const void* p) {
    uint32_t a;
    asm("{ .reg .u64 t; cvta.to.shared.u64 t, %1; cvt.u32.u64 %0, t; }" : "=r"(a) : "l"(p));
    return a;
}
__device__ __forceinline__ void ldsm4(uint32_t* d, uint32_t addr) {
    asm volatile("ldmatrix.sync.aligned.m8n8.x4.shared.b16 {%0,%1,%2,%3}, [%4];"
                 : "=r"(d[0]), "=r"(d[1]), "=r"(d[2]), "=r"(d[3]) : "r"(addr));
}
__device__ __forceinline__ void mma16816(float* c, const uint32_t* a, uint32_t b0, uint32_t b1) {
    asm volatile("mma.sync.aligned.m16n8k16.row.col.f32.f16.f16.f32 "
                 "{%0,%1,%2,%3}, {%4,%5,%6,%7}, {%8,%9}, {%0,%1,%2,%3};"
                 : "+f"(c[0]), "+f"(c[1]), "+f"(c[2]), "+f"(c[3])
                 : "r"(a[0]), "r"(a[1]), "r"(a[2]), "r"(a[3]), "r"(b0), "r"(b1));
}

// ---------------- fp32 -> fp16 convert of x -----------------------------------
__global__ __launch_bounds__(256) void conv_x(const float* __restrict__ x) {
    int i = (blockIdx.x * 256 + threadIdx.x) * 2;
    float2 v = *(const float2*)(x + i);
    __half2 h = __floats2half2_rn(v.x, v.y);
    *(__half2*)((__half*)g_Xh + i) = h;
}

// ---------------- weight packs (tiled transpose to fp16, K-major) -------------
// Wth[j][d], j = head*256+h (heads 0..15 q, 16..31 kv), from src[head][d][h]
__global__ __launch_bounds__(256) void pack_wt(const float* __restrict__ qw,
                                               const float* __restrict__ kvw) {
    __shared__ float t[32][33];
    int d0 = blockIdx.x << 5;
    int h0 = blockIdx.y << 5;
    int hd = blockIdx.z;
    const float* src = (hd < 16) ? (qw + (size_t)hd * 3584 * 256)
                                 : (kvw + (size_t)(hd - 16) * 3584 * 256);
    int c = threadIdx.x & 31, r0 = threadIdx.x >> 5;
#pragma unroll
    for (int r = r0; r < 32; r += 8)
        t[r][c] = src[(size_t)(d0 + r) * 256 + h0 + c];
    __syncthreads();
#pragma unroll
    for (int r = r0; r < 32; r += 8)
        g_Wth[(size_t)(hd * 256 + h0 + r) * 3584 + d0 + c] =
            __half_as_ushort(__float2half(t[c][r]));
}
// OWth[d][j] = ow[j][d], j over 4096 (= n*256+h), d over 3584
__global__ __launch_bounds__(256) void pack_owt(const float* __restrict__ ow) {
    __shared__ float t[32][33];
    int j0 = blockIdx.x << 5;
    int d0 = blockIdx.y << 5;
    int c = threadIdx.x & 31, r0 = threadIdx.x >> 5;
#pragma unroll
    for (int r = r0; r < 32; r += 8)
        t[r][c] = ow[(size_t)(j0 + r) * 3584 + d0 + c];
    __syncthreads();
#pragma unroll
    for (int r = r0; r < 32; r += 8)
        g_OWth[(size_t)(d0 + r) * 4096 + j0 + c] =
            __half_as_ushort(__float2half(t[c][r]));
}

// ---------------- fp16 tensor-core GEMM: C[m][n] = sum_k A[m][k]*Bt[n][k] -----
// CTA tile 128x128, 8 warps (4x2) of 32x64, k-chunk 32, double-buffered cp.async.
#define PITCH 40   // halves per smem row (padded; conflict-free ldmatrix)

__global__ __launch_bounds__(256, 2) void hgemm(const __half* __restrict__ A,
                                                const __half* __restrict__ B,
                                                float* __restrict__ C,
                                                int Nout, int Kdim)
{
    __shared__ __half As[2][128 * PITCH];
    __shared__ __half Bs[2][128 * PITCH];

    const int tid  = threadIdx.x;
    const int lane = tid & 31;
    const int wid  = tid >> 5;
    const int wm = (wid & 3) << 5;      // warp m offset in tile
    const int wn = (wid >> 2) << 6;     // warp n offset in tile
    const int m0 = blockIdx.y << 7;
    const int n0 = blockIdx.x << 7;
    const int nk = Kdim >> 5;

    // cp.async layout: thread -> (row = tid/2, 16-half segment = tid&1)
    const int lrow = tid >> 1;
    const int lcol = (tid & 1) << 4;
    const __half* ag = A + (size_t)(m0 + lrow) * Kdim + lcol;
    const __half* bg = B + (size_t)(n0 + lrow) * Kdim + lcol;

    uint32_t sa0 = smem_u32(&As[0][lrow * PITCH + lcol]);
    uint32_t sa1 = smem_u32(&As[1][lrow * PITCH + lcol]);
    uint32_t sb0 = smem_u32(&Bs[0][lrow * PITCH + lcol]);
    uint32_t sb1 = smem_u32(&Bs[1][lrow * PITCH + lcol]);

    // ldmatrix bases: row = (warp offset + lane&15), col byte = (lane>>4)*16
    const uint32_t lq = lane & 15;
    const uint32_t lh = (lane >> 4) << 4;   // bytes
    uint32_t aB0 = smem_u32(&As[0][(wm + lq) * PITCH]) + lh;
    uint32_t aB1 = smem_u32(&As[1][(wm + lq) * PITCH]) + lh;
    uint32_t bB0 = smem_u32(&Bs[0][(wn + lq) * PITCH]) + lh;
    uint32_t bB1 = smem_u32(&Bs[1][(wn + lq) * PITCH]) + lh;

    float acc[2][8][4];
#pragma unroll
    for (int i = 0; i < 2; i++)
#pragma unroll
        for (int j = 0; j < 8; j++)
#pragma unroll
            for (int q = 0; q < 4; q++) acc[i][j][q] = 0.f;

#define LOAD_STAGE(i) do {                                                        \
    int _buf = (i) & 1;                                                           \
    uint32_t _da = _buf ? sa1 : sa0;                                              \
    uint32_t _db = _buf ? sb1 : sb0;                                              \
    const __half* _a = ag + ((i) << 5);                                           \
    const __half* _b = bg + ((i) << 5);                                           \
    asm volatile("cp.async.cg.shared.global [%0], [%1], 16;\n\t"                  \
                 "cp.async.cg.shared.global [%2], [%3], 16;\n\t"                  \
                 "cp.async.cg.shared.global [%4], [%5], 16;\n\t"                  \
                 "cp.async.cg.shared.global [%6], [%7], 16;\n\t"                  \
                 "cp.async.commit_group;"                                         \
                 :: "r"(_da), "l"(_a), "r"(_da + 16), "l"(_a + 8),                \
                    "r"(_db), "l"(_b), "r"(_db + 16), "l"(_b + 8));               \
} while (0)

    LOAD_STAGE(0);

    for (int i = 0; i < nk; i++) {
        if (i + 1 < nk) {
            LOAD_STAGE(i + 1);
            asm volatile("cp.async.wait_group 1;");
        } else {
            asm volatile("cp.async.wait_group 0;");
        }
        __syncthreads();

        uint32_t ab = (i & 1) ? aB1 : aB0;
        uint32_t bb = (i & 1) ? bB1 : bB0;
#pragma unroll
        for (int ks = 0; ks < 2; ks++) {
            uint32_t af[2][4], bf[4][4];
            ldsm4(af[0], ab + ks * 32);
            ldsm4(af[1], ab + 16 * PITCH * 2 + ks * 32);
#pragma unroll
            for (int p = 0; p < 4; p++)
                ldsm4(bf[p], bb + p * 16 * PITCH * 2 + ks * 32);
#pragma unroll
            for (int mt = 0; mt < 2; mt++)
#pragma unroll
                for (int p = 0; p < 4; p++) {
                    mma16816(acc[mt][2 * p],     af[mt], bf[p][0], bf[p][2]);
                    mma16816(acc[mt][2 * p + 1], af[mt], bf[p][1], bf[p][3]);
                }
        }
        __syncthreads();
    }

    // epilogue: fp32 C
    const int g  = lane >> 2;
    const int cc = (lane & 3) << 1;
#pragma unroll
    for (int mt = 0; mt < 2; mt++) {
        int r = m0 + wm + mt * 16 + g;
#pragma unroll
        for (int nt = 0; nt < 8; nt++) {
            float* cp = C + (size_t)r * Nout + n0 + wn + nt * 8 + cc;
            *(float2*)cp = make_float2(acc[mt][nt][0], acc[mt][nt][1]);
            *(float2*)(cp + (size_t)8 * Nout) = make_float2(acc[mt][nt][2], acc[mt][nt][3]);
        }
    }
}

// ---------------- RoPE (+ q scaling), in place on g_QKV ----------------------
__global__ __launch_bounds__(128) void rope_kernel(const int* __restrict__ segpos)
{
    int bt = blockIdx.x;
    int hh = blockIdx.y;
    int i  = threadIdx.x;
    float* p = g_QKV + (size_t)bt * 8192 + hh * 256;
    float pos = (float)segpos[bt];
    float ts  = powf(10000.0f, (float)i * (1.0f / 128.0f));
    float ang = pos / ts;
    float s, c;
    sincosf(ang, &s, &c);
    float a  = p[i];
    float b2 = p[i + 128];
    float o1 = a * c - b2 * s;
    float o2 = b2 * c + a * s;
    if (hh < 16) { o1 *= 0.0625f; o2 *= 0.0625f; }
    p[i]       = o1;
    p[i + 128] = o2;
}

// ---------------- windowed flash attention (fp32, fp16 ENC epilogue) ---------
#define ATTN_SMEM ((256*64 + 256*32 + 32*256 + 32*68) * 4)

__global__ __launch_bounds__(256) void attn_kernel()
{
    extern __shared__ float sm[];
    float* Qs = sm;
    float* Ks = Qs + 256 * 64;
    float* Vs = Ks + 256 * 32;
    float* Ps = Vs + 32 * 256;

    const int t0  = blockIdx.x << 6;
    const int n   = blockIdx.y;
    const int b   = blockIdx.z;
    const int kh  = n >> 1;
    const int tid = threadIdx.x;

    const float* base = g_QKV + (size_t)b * 2048 * 8192;

    {
        int t  = tid & 63;
        int h0 = (tid >> 6) << 2;
        const float* qp = base + (size_t)(t0 + t) * 8192 + n * 256;
#pragma unroll
        for (int h = h0; h < 256; h += 16) {
            float4 v = *(const float4*)(qp + h);
            Qs[(h + 0) * 64 + t] = v.x;
            Qs[(h + 1) * 64 + t] = v.y;
            Qs[(h + 2) * 64 + t] = v.z;
            Qs[(h + 3) * 64 + t] = v.w;
        }
    }

    const int qt = tid >> 4;
    const int st = tid & 15;

    float m[4] = {-1e30f, -1e30f, -1e30f, -1e30f};
    float l[4] = {0.f, 0.f, 0.f, 0.f};
    float O[4][16];
#pragma unroll
    for (int i = 0; i < 4; i++)
#pragma unroll
        for (int j = 0; j < 16; j++) O[i][j] = 0.f;

    int smin = t0 - 1023; if (smin < 0) smin = 0;
    const int c0 = smin >> 5;
    const int c1 = (t0 + 63) >> 5;

    const int ks  = tid & 31;
    const int kh0 = (tid >> 5) << 2;
    const int vs  = tid >> 3;
    const int vh0 = (tid & 7) << 2;

    for (int c = c0; c <= c1; c++) {
        const int sg0 = c << 5;
        __syncthreads();

        {
            const float* kp = base + (size_t)(sg0 + ks) * 8192 + 4096 + kh * 256;
#pragma unroll
            for (int h = kh0; h < 256; h += 32) {
                float4 v = *(const float4*)(kp + h);
                Ks[(h + 0) * 32 + ks] = v.x;
                Ks[(h + 1) * 32 + ks] = v.y;
                Ks[(h + 2) * 32 + ks] = v.z;
                Ks[(h + 3) * 32 + ks] = v.w;
            }
        }
        {
            const float* vp = base + (size_t)(sg0 + vs) * 8192 + 6144 + kh * 256;
#pragma unroll
            for (int h = vh0; h < 256; h += 32)
                *(float4*)&Vs[vs * 256 + h] = *(const float4*)(vp + h);
        }
        __syncthreads();

        float acc[4][2] = {{0.f,0.f},{0.f,0.f},{0.f,0.f},{0.f,0.f}};
#pragma unroll 8
        for (int h = 0; h < 256; h++) {
            float4 qv = *(const float4*)&Qs[h * 64 + (qt << 2)];
            float2 kv = *(const float2*)&Ks[h * 32 + (st << 1)];
            acc[0][0] = fmaf(qv.x, kv.x, acc[0][0]);
            acc[0][1] = fmaf(qv.x, kv.y, acc[0][1]);
            acc[1][0] = fmaf(qv.y, kv.x, acc[1][0]);
            acc[1][1] = fmaf(qv.y, kv.y, acc[1][1]);
            acc[2][0] = fmaf(qv.z, kv.x, acc[2][0]);
            acc[2][1] = fmaf(qv.z, kv.y, acc[2][1]);
            acc[3][0] = fmaf(qv.w, kv.x, acc[3][0]);
            acc[3][1] = fmaf(qv.w, kv.y, acc[3][1]);
        }

        float alpha[4];
#pragma unroll
        for (int i = 0; i < 4; i++) {
            const int tq = t0 + (qt << 2) + i;
            const int sg = sg0 + (st << 1);
            float v0 = 50.0f * tanhf(acc[i][0] * 0.02f);
            float v1 = 50.0f * tanhf(acc[i][1] * 0.02f);
            bool ok0 = (sg     <= tq) && (sg     >= tq - 1023);
            bool ok1 = (sg + 1 <= tq) && (sg + 1 >= tq - 1023);
            float r0 = ok0 ? v0 : -1e30f;
            float r1 = ok1 ? v1 : -1e30f;
            float rmax = fmaxf(r0, r1);
#pragma unroll
            for (int o = 8; o > 0; o >>= 1)
                rmax = fmaxf(rmax, __shfl_xor_sync(0xffffffffu, rmax, o));
            float mnew = fmaxf(m[i], rmax);
            alpha[i] = __expf(m[i] - mnew);
            float p0 = __expf(r0 - mnew);
            float p1 = __expf(r1 - mnew);
            Ps[(st * 2 + 0) * 68 + (qt << 2) + i] = p0;
            Ps[(st * 2 + 1) * 68 + (qt << 2) + i] = p1;
            float rsum = p0 + p1;
#pragma unroll
            for (int o = 8; o > 0; o >>= 1)
                rsum += __shfl_xor_sync(0xffffffffu, rsum, o);
            l[i] = l[i] * alpha[i] + rsum;
            m[i] = mnew;
        }
        __syncthreads();

#pragma unroll
        for (int i = 0; i < 4; i++) {
            float a = alpha[i];
#pragma unroll
            for (int j = 0; j < 16; j++) O[i][j] *= a;
        }
        for (int s = 0; s < 32; s++) {
            float4 pv = *(const float4*)&Ps[s * 68 + (qt << 2)];
#pragma unroll
            for (int j = 0; j < 4; j++) {
                float4 vv = *(const float4*)&Vs[s * 256 + j * 64 + (st << 2)];
                O[0][j*4+0] = fmaf(pv.x, vv.x, O[0][j*4+0]);
                O[0][j*4+1] = fmaf(pv.x, vv.y, O[0][j*4+1]);
                O[0][j*4+2] = fmaf(pv.x, vv.z, O[0][j*4+2]);
                O[0][j*4+3] = fmaf(pv.x, vv.w, O[0][j*4+3]);
                O[1][j*4+0] = fmaf(pv.y, vv.x, O[1][j*4+0]);
                O[1][j*4+1] = fmaf(pv.y, vv.y, O[1][j*4+1]);
                O[1][j*4+2] = fmaf(pv.y, vv.z, O[1][j*4+2]);
                O[1][j*4+3] = fmaf(pv.y, vv.w, O[1][j*4+3]);
                O[2][j*4+0] = fmaf(pv.z, vv.x, O[2][j*4+0]);
                O[2][j*4+1] = fmaf(pv.z, vv.y, O[2][j*4+1]);
                O[2][j*4+2] = fmaf(pv.z, vv.z, O[2][j*4+2]);
                O[2][j*4+3] = fmaf(pv.z, vv.w, O[2][j*4+3]);
                O[3][j*4+0] = fmaf(pv.w, vv.x, O[3][j*4+0]);
                O[3][j*4+1] = fmaf(pv.w, vv.y, O[3][j*4+1]);
                O[3][j*4+2] = fmaf(pv.w, vv.z, O[3][j*4+2]);
                O[3][j*4+3] = fmaf(pv.w, vv.w, O[3][j*4+3]);
            }
        }
    }

    // epilogue: normalize, store fp16 to g_ENCh[(b*T+t)][n*256+h]
    __half* ep = (__half*)g_ENCh + ((size_t)(b * 2048 + t0)) * 4096 + n * 256;
#pragma unroll
    for (int i = 0; i < 4; i++) {
        float inv = 1.0f / l[i];
        int tq = (qt << 2) + i;
#pragma unroll
        for (int j = 0; j < 4; j++) {
            __half* hp = ep + (size_t)tq * 4096 + j * 64 + (st << 2);
            *(__half2*)(hp + 0) = __floats2half2_rn(O[i][j*4+0] * inv, O[i][j*4+1] * inv);
            *(__half2*)(hp + 2) = __floats2half2_rn(O[i][j*4+2] * inv, O[i][j*4+3] * inv);
        }
    }
}

// ---------------- launch ------------------------------------------------------
extern "C" void kernel_launch(void* const* d_in, const int* in_sizes, int n_in,
                              void* d_out, int out_size)
{
    const float* x      = (const float*)d_in[0];   // (B,T,D) f32
    const int*   segpos = (const int*)  d_in[1];   // (B,T) i32
    const float* qw     = (const float*)d_in[3];   // (N,D,H)
    const float* kvw    = (const float*)d_in[4];   // (2,K,D,H)
    const float* ow     = (const float*)d_in[5];   // (N,H,D)
    float* out = (float*)d_out;                    // (B,T,D)

    void *Xh, *Wth, *OWth, *QKV, *ENCh;
    cudaGetSymbolAddress(&Xh,   g_Xh);
    cudaGetSymbolAddress(&Wth,  g_Wth);
    cudaGetSymbolAddress(&OWth, g_OWth);
    cudaGetSymbolAddress(&QKV,  g_QKV);
    cudaGetSymbolAddress(&ENCh, g_ENCh);

    // 1) convert x, pack weights to fp16 K-major
    conv_x  <<<(4096u * 3584u) / 512, 256>>>(x);
    pack_wt <<<dim3(112, 8, 32), 256>>>(qw, kvw);
    pack_owt<<<dim3(128, 112),   256>>>(ow);

    // 2) qkv = x @ Wt^T : M=4096, N=8192, K=3584 (fp16 HMMA)
    hgemm<<<dim3(8192 / 128, 4096 / 128), 256>>>((const __half*)Xh, (const __half*)Wth,
                                                 (float*)QKV, 8192, 3584);

    // 3) RoPE + q scaling in place
    rope_kernel<<<dim3(4096, 24), 128>>>(segpos);

    // 4) windowed flash attention -> ENC (fp16)
    cudaFuncSetAttribute(attn_kernel, cudaFuncAttributeMaxDynamicSharedMemorySize, ATTN_SMEM);
    attn_kernel<<<dim3(2048 / 64, 16, 2), 256, ATTN_SMEM>>>();

    // 5) out = ENC @ OWt^T : M=4096, N=3584, K=4096 (fp16 HMMA)
    hgemm<<<dim3(3584 / 128, 4096 / 128), 256>>>((const __half*)ENCh, (const __half*)OWth,
                                                 out, 3584, 4096);
}

// round 4
// speedup vs baseline: 6.0319x; 1.9830x over previous
#include <cuda_runtime.h>
#include <cuda_fp16.h>
#include <math.h>
#include <stdint.h>

// B=2, T=2048, D=3584, N=16, K=8, H=256, WINDOW=1024, SOFT_CAP=50, SCALAR=0.0625

// ---------------- scratch (allocation-free device globals) -------------------
__device__ unsigned short g_Xh  [4096u * 3584u];  // x fp16
__device__ unsigned short g_Wth [8192u * 3584u];  // qkv weight [j][d] K-major fp16
__device__ unsigned short g_OWth[3584u * 4096u];  // o_w^T [d][j] K-major fp16
__device__ unsigned short g_QKVh[4096u * 8192u];  // [B*T][ q | k | v ] fp16
__device__ unsigned short g_ENCh[4096u * 4096u];  // attention output fp16

// ---------------- helpers -----------------------------------------------------
__device__ __forceinline__ uint32_t smem_u32(const void* p) {
    uint32_t a;
    asm("{ .reg .u64 t; cvta.to.shared.u64 t, %1; cvt.u32.u64 %0, t; }" : "=r"(a) : "l"(p));
    return a;
}
__device__ __forceinline__ void ldsm4(uint32_t* d, uint32_t addr) {
    asm volatile("ldmatrix.sync.aligned.m8n8.x4.shared.b16 {%0,%1,%2,%3}, [%4];"
                 : "=r"(d[0]), "=r"(d[1]), "=r"(d[2]), "=r"(d[3]) : "r"(addr));
}
__device__ __forceinline__ void ldsm4t(uint32_t* d, uint32_t addr) {
    asm volatile("ldmatrix.sync.aligned.m8n8.x4.trans.shared.b16 {%0,%1,%2,%3}, [%4];"
                 : "=r"(d[0]), "=r"(d[1]), "=r"(d[2]), "=r"(d[3]) : "r"(addr));
}
__device__ __forceinline__ void mma16816(float* c, const uint32_t* a, uint32_t b0, uint32_t b1) {
    asm volatile("mma.sync.aligned.m16n8k16.row.col.f32.f16.f16.f32 "
                 "{%0,%1,%2,%3}, {%4,%5,%6,%7}, {%8,%9}, {%0,%1,%2,%3};"
                 : "+f"(c[0]), "+f"(c[1]), "+f"(c[2]), "+f"(c[3])
                 : "r"(a[0]), "r"(a[1]), "r"(a[2]), "r"(a[3]), "r"(b0), "r"(b1));
}
__device__ __forceinline__ uint32_t f22u(float a, float b) {
    __half2 h = __floats2half2_rn(a, b);
    return *(uint32_t*)&h;
}
__device__ __forceinline__ void cpa16(uint32_t dst, const void* src) {
    asm volatile("cp.async.cg.shared.global [%0], [%1], 16;" :: "r"(dst), "l"(src));
}

// ---------------- fp32 -> fp16 convert of x -----------------------------------
__global__ __launch_bounds__(256) void conv_x(const float* __restrict__ x) {
    int i = (blockIdx.x * 256 + threadIdx.x) * 2;
    float2 v = *(const float2*)(x + i);
    *(__half2*)((__half*)g_Xh + i) = __floats2half2_rn(v.x, v.y);
}

// ---------------- weight packs (tiled transpose to fp16, K-major) -------------
__global__ __launch_bounds__(256) void pack_wt(const float* __restrict__ qw,
                                               const float* __restrict__ kvw) {
    __shared__ float t[32][33];
    int d0 = blockIdx.x << 5;
    int h0 = blockIdx.y << 5;
    int hd = blockIdx.z;
    const float* src = (hd < 16) ? (qw + (size_t)hd * 3584 * 256)
                                 : (kvw + (size_t)(hd - 16) * 3584 * 256);
    int c = threadIdx.x & 31, r0 = threadIdx.x >> 5;
#pragma unroll
    for (int r = r0; r < 32; r += 8)
        t[r][c] = src[(size_t)(d0 + r) * 256 + h0 + c];
    __syncthreads();
#pragma unroll
    for (int r = r0; r < 32; r += 8)
        g_Wth[(size_t)(hd * 256 + h0 + r) * 3584 + d0 + c] =
            __half_as_ushort(__float2half(t[c][r]));
}
__global__ __launch_bounds__(256) void pack_owt(const float* __restrict__ ow) {
    __shared__ float t[32][33];
    int j0 = blockIdx.x << 5;
    int d0 = blockIdx.y << 5;
    int c = threadIdx.x & 31, r0 = threadIdx.x >> 5;
#pragma unroll
    for (int r = r0; r < 32; r += 8)
        t[r][c] = ow[(size_t)(j0 + r) * 3584 + d0 + c];
    __syncthreads();
#pragma unroll
    for (int r = r0; r < 32; r += 8)
        g_OWth[(size_t)(d0 + r) * 4096 + j0 + c] =
            __half_as_ushort(__float2half(t[c][r]));
}

// ---------------- fp16 HMMA GEMM, 3-stage cp.async, 1 sync/iter ---------------
#define PITCH 40
#define STAGE_B 20480            // bytes per stage (A 5120 + B 5120 halves)
#define HGEMM_SMEM (3 * STAGE_B) // 61440

template <typename CT>
__global__ __launch_bounds__(256, 2) void hgemm(const __half* __restrict__ A,
                                                const __half* __restrict__ B,
                                                CT* __restrict__ C,
                                                int Nout, int Kdim)
{
    extern __shared__ __half hsm[];

    const int tid  = threadIdx.x;
    const int lane = tid & 31;
    const int wid  = tid >> 5;
    const int wm = (wid & 3) << 5;
    const int wn = (wid >> 2) << 6;
    const int m0 = blockIdx.y << 7;
    const int n0 = blockIdx.x << 7;
    const int nk = Kdim >> 5;

    const int lrow = tid >> 1;
    const int lcol = (tid & 1) << 4;
    const __half* ag = A + (size_t)(m0 + lrow) * Kdim + lcol;
    const __half* bg = B + (size_t)(n0 + lrow) * Kdim + lcol;

    uint32_t sb0 = smem_u32(hsm);
    uint32_t sa  = sb0 + (lrow * PITCH + lcol) * 2;
    uint32_t sbq = sa + 10240;

    const uint32_t lq = lane & 15;
    const uint32_t lh = (lane >> 4) << 4;
    uint32_t abase = sb0 + ((wm + lq) * PITCH) * 2 + lh;
    uint32_t bbase = sb0 + 10240 + ((wn + lq) * PITCH) * 2 + lh;

    float acc[2][8][4];
#pragma unroll
    for (int i = 0; i < 2; i++)
#pragma unroll
        for (int j = 0; j < 8; j++)
#pragma unroll
            for (int q = 0; q < 4; q++) acc[i][j][q] = 0.f;

#define HLOAD(i, s) do {                                                          \
    uint32_t _da = sa + (s) * STAGE_B;                                            \
    uint32_t _db = sbq + (s) * STAGE_B;                                           \
    const __half* _a = ag + ((i) << 5);                                           \
    const __half* _b = bg + ((i) << 5);                                           \
    asm volatile("cp.async.cg.shared.global [%0], [%1], 16;\n\t"                  \
                 "cp.async.cg.shared.global [%2], [%3], 16;\n\t"                  \
                 "cp.async.cg.shared.global [%4], [%5], 16;\n\t"                  \
                 "cp.async.cg.shared.global [%6], [%7], 16;\n\t"                  \
                 "cp.async.commit_group;"                                         \
                 :: "r"(_da), "l"(_a), "r"(_da + 16), "l"(_a + 8),                \
                    "r"(_db), "l"(_b), "r"(_db + 16), "l"(_b + 8));               \
} while (0)

    HLOAD(0, 0);
    HLOAD(1, 1);

    for (int i = 0; i < nk; i++) {
        if (i + 1 < nk) asm volatile("cp.async.wait_group 1;");
        else            asm volatile("cp.async.wait_group 0;");
        __syncthreads();
        if (i + 2 < nk) HLOAD(i + 2, (i + 2) % 3);

        uint32_t so = (uint32_t)(i % 3) * STAGE_B;
        uint32_t ab = abase + so;
        uint32_t bb = bbase + so;
#pragma unroll
        for (int ks = 0; ks < 2; ks++) {
            uint32_t af[2][4], bf[4][4];
            ldsm4(af[0], ab + ks * 32);
            ldsm4(af[1], ab + 16 * PITCH * 2 + ks * 32);
#pragma unroll
            for (int p = 0; p < 4; p++)
                ldsm4(bf[p], bb + p * 16 * PITCH * 2 + ks * 32);
#pragma unroll
            for (int mt = 0; mt < 2; mt++)
#pragma unroll
                for (int p = 0; p < 4; p++) {
                    mma16816(acc[mt][2 * p],     af[mt], bf[p][0], bf[p][2]);
                    mma16816(acc[mt][2 * p + 1], af[mt], bf[p][1], bf[p][3]);
                }
        }
    }

    const int g  = lane >> 2;
    const int cc = (lane & 3) << 1;
#pragma unroll
    for (int mt = 0; mt < 2; mt++) {
        int r = m0 + wm + mt * 16 + g;
#pragma unroll
        for (int nt = 0; nt < 8; nt++) {
            size_t off = (size_t)r * Nout + n0 + wn + nt * 8 + cc;
            if (sizeof(CT) == 2) {
                __half* cp = (__half*)C + off;
                *(uint32_t*)cp = f22u(acc[mt][nt][0], acc[mt][nt][1]);
                *(uint32_t*)(cp + (size_t)8 * Nout) = f22u(acc[mt][nt][2], acc[mt][nt][3]);
            } else {
                float* cp = (float*)C + off;
                *(float2*)cp = make_float2(acc[mt][nt][0], acc[mt][nt][1]);
                *(float2*)(cp + (size_t)8 * Nout) = make_float2(acc[mt][nt][2], acc[mt][nt][3]);
            }
        }
    }
}

// ---------------- RoPE (+ q scaling), in place on fp16 QKV --------------------
__global__ __launch_bounds__(128) void rope_kernel(const int* __restrict__ segpos)
{
    int bt = blockIdx.x;
    int hh = blockIdx.y;          // 0..23: q heads 0-15, k heads 16-23 (contiguous)
    int i  = threadIdx.x;
    __half* p = (__half*)g_QKVh + (size_t)bt * 8192 + hh * 256;
    float pos = (float)segpos[bt];
    float ts  = powf(10000.0f, (float)i * (1.0f / 128.0f));
    float ang = pos / ts;
    float s, c;
    sincosf(ang, &s, &c);
    float a  = __half2float(p[i]);
    float b2 = __half2float(p[i + 128]);
    float o1 = a * c - b2 * s;
    float o2 = b2 * c + a * s;
    if (hh < 16) { o1 *= 0.0625f; o2 *= 0.0625f; }
    p[i]       = __float2half(o1);
    p[i + 128] = __float2half(o2);
}

// ---------------- fp16 tensor-core flash attention ----------------------------
// grid (16, 16, 2); 256 threads; 128-query tile, 64-key chunks, double-buffered.
#define APITCH 264
#define KS_OFF (128 * APITCH)
#define KS_SZ  (64 * APITCH)
#define VS_OFF (KS_OFF + 2 * KS_SZ)
#define ATTN_SMEM ((KS_OFF + 4 * KS_SZ) * 2)   // 202752 bytes

__global__ __launch_bounds__(256, 1) void attn_kernel()
{
    extern __shared__ __half ash[];
    const int tid  = threadIdx.x;
    const int lane = tid & 31;
    const int w    = tid >> 5;
    const int t0   = blockIdx.x << 7;
    const int n    = blockIdx.y;
    const int b    = blockIdx.z;
    const int kh   = n >> 1;
    uint32_t sb = smem_u32(ash);

    const __half* qkvh = (const __half*)g_QKVh + (size_t)b * 2048 * 8192;

    // Q tile load (part of first cp.async group)
    {
        const __half* qs = qkvh + (size_t)t0 * 8192 + n * 256;
#pragma unroll
        for (int it = 0; it < 16; it++) {
            int slot = it * 256 + tid;
            int r = slot >> 5, cs = (slot & 31) << 3;
            cpa16(sb + (r * APITCH + cs) * 2, qs + (size_t)r * 8192 + cs);
        }
    }

    int smin = t0 - 1023; if (smin < 0) smin = 0;
    const int c0 = smin >> 6, c1 = (t0 + 127) >> 6;

    const int ldr = tid >> 5, ldc = (tid & 31) << 3;   // K/V loader: 8 rows/pass

#define LOADKV(sg0, bf) do {                                                       \
    const __half* _ks = qkvh + (size_t)(sg0) * 8192 + 4096 + kh * 256;             \
    uint32_t _kb = sb + (KS_OFF + (bf) * KS_SZ) * 2;                               \
    uint32_t _vb = sb + (VS_OFF + (bf) * KS_SZ) * 2;                               \
    _Pragma("unroll")                                                              \
    for (int _it = 0; _it < 8; _it++) {                                            \
        int _r = _it * 8 + ldr;                                                    \
        cpa16(_kb + (_r * APITCH + ldc) * 2, _ks + (size_t)_r * 8192 + ldc);       \
        cpa16(_vb + (_r * APITCH + ldc) * 2, _ks + (size_t)_r * 8192 + 2048 + ldc);\
    }                                                                              \
    asm volatile("cp.async.commit_group;");                                        \
} while (0)

    LOADKV(c0 << 6, 0);

    float of[32][4];
#pragma unroll
    for (int f = 0; f < 32; f++)
#pragma unroll
        for (int q = 0; q < 4; q++) of[f][q] = 0.f;
    float m0 = -1e30f, m1 = -1e30f, l0 = 0.f, l1 = 0.f;

    const uint32_t lq  = lane & 15;
    const uint32_t lh16 = (lane >> 4) << 4;
    uint32_t qb  = sb + (((w << 4) + lq) * APITCH) * 2 + lh16;
    uint32_t kvl = (lq * APITCH) * 2 + lh16;

    const int row0 = t0 + (w << 4) + (lane >> 2);
    const int row1 = row0 + 8;
    const int colq = (lane & 3) << 1;
    const int wr0 = t0 + (w << 4), wr1 = wr0 + 15;

    int buf = 0;
    for (int c = c0; c <= c1; c++) {
        const int sg0 = c << 6;
        if (c < c1) {
            LOADKV((c + 1) << 6, buf ^ 1);
            asm volatile("cp.async.wait_group 1;");
        } else {
            asm volatile("cp.async.wait_group 0;");
        }
        __syncthreads();

        if (sg0 <= wr1 && sg0 + 63 >= wr0 - 1023) {
            uint32_t kb = sb + (KS_OFF + buf * KS_SZ) * 2 + kvl;
            uint32_t vb = sb + (VS_OFF + buf * KS_SZ) * 2 + kvl;

            float sf[8][4];
#pragma unroll
            for (int j = 0; j < 8; j++)
#pragma unroll
                for (int q = 0; q < 4; q++) sf[j][q] = 0.f;

#pragma unroll
            for (int kk = 0; kk < 16; kk++) {
                uint32_t a[4];
                ldsm4(a, qb + kk * 32);
#pragma unroll
                for (int ng = 0; ng < 4; ng++) {
                    uint32_t bfr[4];
                    ldsm4(bfr, kb + ng * (16 * APITCH * 2) + kk * 32);
                    mma16816(sf[ng * 2],     a, bfr[0], bfr[2]);
                    mma16816(sf[ng * 2 + 1], a, bfr[1], bfr[3]);
                }
            }

            // soft cap + mask + online softmax (fp32)
            float mx0 = -1e30f, mx1 = -1e30f;
#pragma unroll
            for (int j = 0; j < 8; j++) {
                int col = sg0 + j * 8 + colq;
#pragma unroll
                for (int q = 0; q < 4; q++) {
                    float e = __expf(sf[j][q] * 0.04f);          // exp(2*z), z=s/50
                    float s = 50.f * __fdividef(e - 1.f, e + 1.f);
                    int rr = (q < 2) ? row0 : row1;
                    int cc2 = col + (q & 1);
                    bool ok = (cc2 <= rr) && (cc2 >= rr - 1023);
                    sf[j][q] = ok ? s : -1e30f;
                }
                mx0 = fmaxf(mx0, fmaxf(sf[j][0], sf[j][1]));
                mx1 = fmaxf(mx1, fmaxf(sf[j][2], sf[j][3]));
            }
            mx0 = fmaxf(mx0, __shfl_xor_sync(~0u, mx0, 1));
            mx0 = fmaxf(mx0, __shfl_xor_sync(~0u, mx0, 2));
            mx1 = fmaxf(mx1, __shfl_xor_sync(~0u, mx1, 1));
            mx1 = fmaxf(mx1, __shfl_xor_sync(~0u, mx1, 2));

            float mn0 = fmaxf(m0, mx0), mn1 = fmaxf(m1, mx1);
            float a0 = __expf(m0 - mn0), a1 = __expf(m1 - mn1);
            m0 = mn0; m1 = mn1;

            float rs0 = 0.f, rs1 = 0.f;
#pragma unroll
            for (int j = 0; j < 8; j++) {
                sf[j][0] = __expf(sf[j][0] - mn0); rs0 += sf[j][0];
                sf[j][1] = __expf(sf[j][1] - mn0); rs0 += sf[j][1];
                sf[j][2] = __expf(sf[j][2] - mn1); rs1 += sf[j][2];
                sf[j][3] = __expf(sf[j][3] - mn1); rs1 += sf[j][3];
            }
            rs0 += __shfl_xor_sync(~0u, rs0, 1);
            rs0 += __shfl_xor_sync(~0u, rs0, 2);
            rs1 += __shfl_xor_sync(~0u, rs1, 1);
            rs1 += __shfl_xor_sync(~0u, rs1, 2);
            l0 = l0 * a0 + rs0;
            l1 = l1 * a1 + rs1;

#pragma unroll
            for (int f = 0; f < 32; f++) {
                of[f][0] *= a0; of[f][1] *= a0;
                of[f][2] *= a1; of[f][3] *= a1;
            }

            // P -> fp16 A-frags (standard FA2 frag pairing)
            uint32_t pa[4][4];
#pragma unroll
            for (int sj = 0; sj < 4; sj++) {
                pa[sj][0] = f22u(sf[2 * sj][0],     sf[2 * sj][1]);
                pa[sj][1] = f22u(sf[2 * sj][2],     sf[2 * sj][3]);
                pa[sj][2] = f22u(sf[2 * sj + 1][0], sf[2 * sj + 1][1]);
                pa[sj][3] = f22u(sf[2 * sj + 1][2], sf[2 * sj + 1][3]);
            }

            // O += P @ V   (V via ldmatrix.trans)
#pragma unroll
            for (int sj = 0; sj < 4; sj++) {
#pragma unroll
                for (int hg = 0; hg < 16; hg++) {
                    uint32_t v[4];
                    ldsm4t(v, vb + sj * (16 * APITCH * 2) + hg * 32);
                    mma16816(of[hg * 2],     pa[sj], v[0], v[1]);
                    mma16816(of[hg * 2 + 1], pa[sj], v[2], v[3]);
                }
            }
        }
        __syncthreads();
        buf ^= 1;
    }

    // epilogue: normalize, write fp16 ENC
    float i0 = 1.f / l0, i1 = 1.f / l1;
    __half* ENC = (__half*)g_ENCh;
    size_t base0 = ((size_t)(b * 2048) + row0) * 4096 + n * 256 + colq;
    size_t base1 = ((size_t)(b * 2048) + row1) * 4096 + n * 256 + colq;
#pragma unroll
    for (int f = 0; f < 32; f++) {
        *(uint32_t*)(ENC + base0 + f * 8) = f22u(of[f][0] * i0, of[f][1] * i0);
        *(uint32_t*)(ENC + base1 + f * 8) = f22u(of[f][2] * i1, of[f][3] * i1);
    }
}

// ---------------- launch ------------------------------------------------------
extern "C" void kernel_launch(void* const* d_in, const int* in_sizes, int n_in,
                              void* d_out, int out_size)
{
    const float* x      = (const float*)d_in[0];
    const int*   segpos = (const int*)  d_in[1];
    const float* qw     = (const float*)d_in[3];
    const float* kvw    = (const float*)d_in[4];
    const float* ow     = (const float*)d_in[5];
    float* out = (float*)d_out;

    void *Xh, *Wth, *OWth, *QKVh, *ENCh;
    cudaGetSymbolAddress(&Xh,   g_Xh);
    cudaGetSymbolAddress(&Wth,  g_Wth);
    cudaGetSymbolAddress(&OWth, g_OWth);
    cudaGetSymbolAddress(&QKVh, g_QKVh);
    cudaGetSymbolAddress(&ENCh, g_ENCh);

    conv_x  <<<(4096u * 3584u) / 512, 256>>>(x);
    pack_wt <<<dim3(112, 8, 32), 256>>>(qw, kvw);
    pack_owt<<<dim3(128, 112),   256>>>(ow);

    cudaFuncSetAttribute(hgemm<__half>, cudaFuncAttributeMaxDynamicSharedMemorySize, HGEMM_SMEM);
    cudaFuncSetAttribute(hgemm<float>,  cudaFuncAttributeMaxDynamicSharedMemorySize, HGEMM_SMEM);
    cudaFuncSetAttribute(attn_kernel,   cudaFuncAttributeMaxDynamicSharedMemorySize, ATTN_SMEM);

    // qkv = x @ Wt^T -> fp16
    hgemm<__half><<<dim3(8192 / 128, 4096 / 128), 256, HGEMM_SMEM>>>(
        (const __half*)Xh, (const __half*)Wth, (__half*)QKVh, 8192, 3584);

    // RoPE + q scaling in place (fp16)
    rope_kernel<<<dim3(4096, 24), 128>>>(segpos);

    // fp16 flash attention -> ENCh
    attn_kernel<<<dim3(16, 16, 2), 256, ATTN_SMEM>>>();

    // out = ENC @ OWt^T -> fp32
    hgemm<float><<<dim3(3584 / 128, 4096 / 128), 256, HGEMM_SMEM>>>(
        (const __half*)ENCh, (const __half*)OWth, out, 3584, 4096);
}